// round 15
// baseline (speedup 1.0000x reference)
#include <cuda_runtime.h>
#include <cstdint>

typedef unsigned long long ull;

// ---------- packed f32x2 helpers (sm_10x; ptxas never emits FFMA2 from C++) ----------
static __device__ __forceinline__ ull pk(float lo, float hi) {
    ull r; asm("mov.b64 %0,{%1,%2};" : "=l"(r) : "f"(lo), "f"(hi)); return r;
}
static __device__ __forceinline__ void upk(ull v, float& lo, float& hi) {
    asm("mov.b64 {%0,%1},%2;" : "=f"(lo), "=f"(hi) : "l"(v));
}
static __device__ __forceinline__ ull fma2(ull a, ull b, ull c) {
    ull d; asm("fma.rn.f32x2 %0,%1,%2,%3;" : "=l"(d) : "l"(a), "l"(b), "l"(c)); return d;
}
static __device__ __forceinline__ ull mul2(ull a, ull b) {
    ull d; asm("mul.rn.f32x2 %0,%1,%2;" : "=l"(d) : "l"(a), "l"(b)); return d;
}

#define TPB  128          // 4 warps
#define RPB  256          // rows per block (2 per thread)
#define NW   (TPB/32)
#define PADR 10           // smem floats per 8-col chunk row (even -> 8B-aligned float2 reads)

__global__ __launch_bounds__(TPB, 5)
void qubit_bloch_kernel(const float* __restrict__ x,
                        const float* __restrict__ theta,
                        const float* __restrict__ w,
                        const float* __restrict__ bias,
                        float* __restrict__ out,
                        int B) {
    // per-warp double-buffered chunk storage: 64 rows x PADR floats
    __shared__ float  s_x[NW][2][64 * PADR];   // 4*2*2560B = 20.0 KB
    __shared__ float2 s_c[32 * 8];             // 2 KB duplicated f32x2 step constants

    const int  tid  = threadIdx.x;
    const int  l    = tid & 31;
    const int  wd   = tid >> 5;
    const long base = (long)blockIdx.x * RPB;

    // ---- warp 0: per-step RZ(c)∘RY(b) Bloch-rotation constants (theta tiny -> fast path) ----
    if (tid < 32) {
        float sb, cb, sc, cc;
        sincosf(theta[2 * tid + 0], &sb, &cb);
        sincosf(theta[2 * tid + 1], &sc, &cc);
        float2* p = &s_c[tid * 8];
        p[0] = make_float2(cc * cb, cc * cb);
        p[1] = make_float2(cc * sb, cc * sb);
        p[2] = make_float2(-sc, -sc);
        p[3] = make_float2(sc * cb, sc * cb);
        p[4] = make_float2(sc * sb, sc * sb);
        p[5] = make_float2(cc, cc);
        p[6] = make_float2(-sb, -sb);
        p[7] = make_float2(cb, cb);
    }

    // Bloch state (packed 2 elements/thread): start (0,0,1)
    ull X = pk(0.0f, 0.0f);
    ull Y = X;
    ull Z = pk(1.0f, 1.0f);

    if (base + RPB <= (long)B) {
        // =========================== fast path ===========================
        const float4* gx4 = (const float4*)x;

        // lane's 4 float4 slots per chunk: flat = j*32+l -> (row-half h, local row lr)
        long gidx[4]; int soff[4];
        #pragma unroll
        for (int j = 0; j < 4; j++) {
            int flat = j * 32 + l;
            int h    = flat & 1;
            int lr   = flat >> 1;                       // 0..63
            long gr  = (lr < 32) ? (base + 32 * wd + lr)
                                 : (base + 128 + 32 * wd + (lr - 32));
            gidx[j]  = gr * 8 + h;                      // f4 index (add c*2 per chunk)
            soff[j]  = lr * PADR + h * 4;
        }

        float4 v[4];
        // prologue: chunk 0 in flight
        #pragma unroll
        for (int j = 0; j < 4; j++) v[j] = __ldcs(&gx4[gidx[j] + 0]);
        __syncthreads();                                // constants ready (LDGs already in flight)
        #pragma unroll
        for (int j = 0; j < 4; j++) {
            float* p = &s_x[wd][0][soff[j]];
            p[0] = v[j].x; p[1] = v[j].y; p[2] = v[j].z; p[3] = v[j].w;
        }
        __syncwarp();
        // chunk 1 in flight
        #pragma unroll
        for (int j = 0; j < 4; j++) v[j] = __ldcs(&gx4[gidx[j] + 2]);

        const float* rowA = &s_x[wd][0][l * PADR];        // element A: local row l
        const float* rowB = &s_x[wd][0][(32 + l) * PADR]; // element B: local row 32+l
        const int bufStride = 64 * PADR;

        #pragma unroll
        for (int c = 0; c < 4; c++) {
            const float* rA = rowA + (c & 1) * bufStride;
            const float* rB = rowB + (c & 1) * bufStride;
            #pragma unroll
            for (int tt = 0; tt < 8; tt += 2) {
                float2 xA = *(const float2*)&rA[tt];      // conflict-free (pad 10)
                float2 xB = *(const float2*)&rB[tt];
                #pragma unroll
                for (int u = 0; u < 2; u++) {
                    const int t = c * 8 + tt + u;
                    float xa = u ? xA.y : xA.x;
                    float xb = u ? xB.y : xB.x;
                    float sxa, cxa, sxb, cxb;
                    __sincosf(xa, &sxa, &cxa);
                    __sincosf(xb, &sxb, &cxb);
                    ull cx  = pk(cxa, cxb);
                    ull sx  = pk(sxa, sxb);
                    ull nsx = pk(-sxa, -sxb);
                    const ulonglong2* C = (const ulonglong2*)&s_c[t * 8]; // 4x LDS.128 bcast
                    ulonglong2 a  = C[0];   // C0,C1
                    ulonglong2 b2 = C[1];   // C2,C3
                    ulonglong2 d2 = C[2];   // C4,C5
                    ulonglong2 e2 = C[3];   // C6,C7
                    ull Y1 = fma2(cx, Y, mul2(nsx, Z));
                    ull Z1 = fma2(cx, Z, mul2(sx, Y));
                    ull Xn = fma2(a.x,  X, fma2(a.y,  Z1, mul2(b2.x, Y1)));
                    ull Yn = fma2(b2.y, X, fma2(d2.x, Z1, mul2(d2.y, Y1)));
                    ull Zn = fma2(e2.y, Z1, mul2(e2.x, X));
                    X = Xn; Y = Yn; Z = Zn;
                }
            }
            if (c < 3) {
                // drain chunk c+1 into the other buffer, then prefetch chunk c+2
                #pragma unroll
                for (int j = 0; j < 4; j++) {
                    float* p = &s_x[wd][(c + 1) & 1][soff[j]];
                    p[0] = v[j].x; p[1] = v[j].y; p[2] = v[j].z; p[3] = v[j].w;
                }
                __syncwarp();
                if (c < 2) {
                    #pragma unroll
                    for (int j = 0; j < 4; j++) v[j] = __ldcs(&gx4[gidx[j] + (c + 2) * 2]);
                }
            }
        }

        float za, zb;
        upk(Z, za, zb);
        const float ww = __ldg(w);
        const float bb = __ldg(bias);
        __stcs(&out[base + tid],       za * ww + bb);
        __stcs(&out[base + TPB + tid], zb * ww + bb);
    } else {
        // =========================== tail path (cold, scalar) ===========================
        __syncthreads();   // constants ready
        const float ww = __ldg(w);
        const float bb = __ldg(bias);
        #pragma unroll
        for (int e = 0; e < 2; e++) {
            long r = base + tid + (long)e * TPB;
            if (r < B) {
                float Xs = 0.0f, Ys = 0.0f, Zs = 1.0f;
                for (int t = 0; t < 32; t++) {
                    float xa = x[r * 32 + t];
                    float sxa, cxa;
                    __sincosf(xa, &sxa, &cxa);
                    const float2* C = &s_c[t * 8];
                    float Y1 = cxa * Ys - sxa * Zs;
                    float Z1 = sxa * Ys + cxa * Zs;
                    float Xn = C[0].x * Xs + C[1].x * Z1 + C[2].x * Y1;
                    float Yn = C[3].x * Xs + C[4].x * Z1 + C[5].x * Y1;
                    float Zn = C[6].x * Xs + C[7].x * Z1;
                    Xs = Xn; Ys = Yn; Zs = Zn;
                }
                out[r] = Zs * ww + bb;
            }
        }
    }
}

extern "C" void kernel_launch(void* const* d_in, const int* in_sizes, int n_in,
                              void* d_out, int out_size) {
    const float* x     = (const float*)d_in[0];   // [B, 32] f32
    const float* theta = (const float*)d_in[1];   // [32, 2] f32
    const float* w     = (const float*)d_in[2];   // [1, 1]  f32
    const float* b     = (const float*)d_in[3];   // [1]     f32
    float* out = (float*)d_out;

    const int B = in_sizes[0] / 32;
    const int blocks = (B + RPB - 1) / RPB;
    qubit_bloch_kernel<<<blocks, TPB>>>(x, theta, w, b, out, B);
}

// round 16
// speedup vs baseline: 1.4256x; 1.4256x over previous
#include <cuda_runtime.h>
#include <cstdint>

typedef unsigned long long ull;

// ---------- packed f32x2 helpers (sm_10x; ptxas never emits FFMA2 from C++) ----------
static __device__ __forceinline__ ull pk(float lo, float hi) {
    ull r; asm("mov.b64 %0,{%1,%2};" : "=l"(r) : "f"(lo), "f"(hi)); return r;
}
static __device__ __forceinline__ void upk(ull v, float& lo, float& hi) {
    asm("mov.b64 {%0,%1},%2;" : "=f"(lo), "=f"(hi) : "l"(v));
}
static __device__ __forceinline__ ull fma2(ull a, ull b, ull c) {
    ull d; asm("fma.rn.f32x2 %0,%1,%2,%3;" : "=l"(d) : "l"(a), "l"(b), "l"(c)); return d;
}
static __device__ __forceinline__ ull mul2(ull a, ull b) {
    ull d; asm("mul.rn.f32x2 %0,%1,%2;" : "=l"(d) : "l"(a), "l"(b)); return d;
}

static __device__ __forceinline__ unsigned smem_u32(const void* p) {
    unsigned a;
    asm("{ .reg .u64 t; cvta.to.shared.u64 t, %1; cvt.u32.u64 %0, t; }" : "=r"(a) : "l"(p));
    return a;
}
static __device__ __forceinline__ void cp_async16(unsigned dst, const void* src) {
    asm volatile("cp.async.cg.shared.global [%0], [%1], 16;" :: "r"(dst), "l"(src));
}
static __device__ __forceinline__ void cp_commit() {
    asm volatile("cp.async.commit_group;");
}
template <int N> static __device__ __forceinline__ void cp_wait() {
    asm volatile("cp.async.wait_group %0;" :: "n"(N));
}

#define TPB   128                 // 4 warps
#define RPB   256                 // rows per tile (2 per thread)
#define TILEF (RPB * 32)          // floats per tile buffer (8192) — XOR swizzle, no pad
#define SMEMB (2 * TILEF * 4 + 32 * 8 * 8)   // 65536 + 2048 = 67584 B

__global__ __launch_bounds__(TPB)
void qubit_bloch_kernel(const float* __restrict__ x,
                        const float* __restrict__ theta,
                        const float* __restrict__ w,
                        const float* __restrict__ bias,
                        float* __restrict__ out,
                        int B, int ntiles) {
    extern __shared__ float sm[];             // [2*TILEF] x buffers, then s_c
    float2* s_c = (float2*)&sm[2 * TILEF];    // 32 steps x 8 duplicated f32x2 constants

    const int tid = threadIdx.x;
    const int G   = gridDim.x;

    // ---- per-step RZ(c)∘RY(b) Bloch-rotation constants (once per block) ----
    if (tid < 32) {
        float sb, cb, sc, cc;
        sincosf(theta[2 * tid + 0], &sb, &cb);
        sincosf(theta[2 * tid + 1], &sc, &cc);
        float2* p = &s_c[tid * 8];
        p[0] = make_float2(cc * cb, cc * cb);
        p[1] = make_float2(cc * sb, cc * sb);
        p[2] = make_float2(-sc, -sc);
        p[3] = make_float2(sc * cb, sc * cb);
        p[4] = make_float2(sc * sb, sc * sb);
        p[5] = make_float2(cc, cc);
        p[6] = make_float2(-sb, -sb);
        p[7] = make_float2(cb, cb);
    }

    // precompute this thread's 16 staging slots (row r = k>>3, quad q = k&7)
    // smem float4 slot is XOR-swizzled: slot' = q ^ (r & 7)  -> 16B-aligned cp.async dst
    unsigned dstoff[16];      // byte offsets within a tile buffer
    int      srcoff[16];      // float offsets within a tile's gmem region
    #pragma unroll
    for (int i = 0; i < 16; i++) {
        int k = i * TPB + tid;
        int r = k >> 3, q = k & 7;
        dstoff[i] = (unsigned)((r * 32 + ((q ^ (r & 7)) << 2)) * 4);
        srcoff[i] = r * 32 + q * 4;
    }
    const unsigned sbase = smem_u32(sm);
    const float ww = __ldg(w);
    const float bb = __ldg(bias);

    long tile = blockIdx.x;
    if (tile >= ntiles) return;

    // ---- prologue: stage tile 0 into buffer 0 ----
    {
        const float* src = x + tile * (long)TILEF;
        long rem = (long)B - tile * RPB;                  // rows available
        #pragma unroll
        for (int i = 0; i < 16; i++) {
            const float* s = ((srcoff[i] >> 5) < rem) ? (src + srcoff[i]) : x;
            cp_async16(sbase + dstoff[i], s);
        }
        cp_commit();
    }

    int pbuf = 0;
    for (; tile < ntiles; tile += G) {
        const long next = tile + G;
        const bool have_next = next < ntiles;

        if (have_next) {     // stage next tile into the other buffer (overlaps this compute)
            const float* src = x + next * (long)TILEF;
            long rem = (long)B - next * RPB;
            const unsigned nb = sbase + (unsigned)(pbuf ^ 1) * (TILEF * 4);
            #pragma unroll
            for (int i = 0; i < 16; i++) {
                const float* s = ((srcoff[i] >> 5) < rem) ? (src + srcoff[i]) : x;
                cp_async16(nb + dstoff[i], s);
            }
            cp_commit();
            cp_wait<1>();    // current tile's group done; next stays in flight
        } else {
            cp_wait<0>();
        }
        __syncthreads();     // tile data + (first iter) constants visible

        // ---- compute: 2 rows/thread, packed f32x2 Bloch state, swizzled LDS.128 reads ----
        const float* buf = &sm[pbuf * TILEF];
        const int rA = tid, rB = tid + TPB;
        ull X = pk(0.0f, 0.0f);
        ull Y = X;
        ull Z = pk(1.0f, 1.0f);

        #pragma unroll
        for (int g = 0; g < 8; g++) {          // 8 groups of 4 steps
            float4 a4 = *(const float4*)&buf[rA * 32 + ((g ^ (rA & 7)) << 2)];
            float4 b4 = *(const float4*)&buf[rB * 32 + ((g ^ (rB & 7)) << 2)];
            const float xav[4] = {a4.x, a4.y, a4.z, a4.w};
            const float xbv[4] = {b4.x, b4.y, b4.z, b4.w};
            #pragma unroll
            for (int u = 0; u < 4; u++) {
                const int t = g * 4 + u;
                float sxa, cxa, sxb, cxb;
                __sincosf(xav[u], &sxa, &cxa);
                __sincosf(xbv[u], &sxb, &cxb);
                ull cx  = pk(cxa, cxb);
                ull sx  = pk(sxa, sxb);
                ull nsx = pk(-sxa, -sxb);
                const ulonglong2* C = (const ulonglong2*)&s_c[t * 8];  // 4x LDS.128 bcast
                ulonglong2 c0 = C[0], c1 = C[1], c2 = C[2], c3 = C[3];
                ull Y1 = fma2(cx, Y, mul2(nsx, Z));
                ull Z1 = fma2(cx, Z, mul2(sx, Y));
                ull Xn = fma2(c0.x, X, fma2(c0.y, Z1, mul2(c1.x, Y1)));
                ull Yn = fma2(c1.y, X, fma2(c2.x, Z1, mul2(c2.y, Y1)));
                ull Zn = fma2(c3.y, Z1, mul2(c3.x, X));
                X = Xn; Y = Yn; Z = Zn;
            }
        }

        float za, zb;
        upk(Z, za, zb);
        const long base = tile * RPB;
        if (base + tid < B)       __stcs(&out[base + tid],       za * ww + bb);
        if (base + TPB + tid < B) __stcs(&out[base + TPB + tid], zb * ww + bb);

        __syncthreads();     // all reads of buf[pbuf] done before it is restaged (iter+2)
        pbuf ^= 1;
    }
}

extern "C" void kernel_launch(void* const* d_in, const int* in_sizes, int n_in,
                              void* d_out, int out_size) {
    const float* x     = (const float*)d_in[0];   // [B, 32] f32
    const float* theta = (const float*)d_in[1];   // [32, 2] f32
    const float* w     = (const float*)d_in[2];   // [1, 1]  f32
    const float* b     = (const float*)d_in[3];   // [1]     f32
    float* out = (float*)d_out;

    const int B = in_sizes[0] / 32;
    const int ntiles = (B + RPB - 1) / RPB;

    static int smem_set = 0;
    if (!smem_set) {
        cudaFuncSetAttribute(qubit_bloch_kernel,
                             cudaFuncAttributeMaxDynamicSharedMemorySize, SMEMB);
        smem_set = 1;
    }

    const int persistent = 148 * 3;               // 3 blocks/SM (67.6 KB smem each)
    const int blocks = ntiles < persistent ? ntiles : persistent;
    qubit_bloch_kernel<<<blocks, TPB, SMEMB>>>(x, theta, w, b, out, B, ntiles);
}

// round 17
// speedup vs baseline: 1.4365x; 1.0077x over previous
#include <cuda_runtime.h>
#include <cstdint>

typedef unsigned long long ull;

// ---------- packed f32x2 helpers (sm_10x; ptxas never emits FFMA2 from C++) ----------
static __device__ __forceinline__ ull pk(float lo, float hi) {
    ull r; asm("mov.b64 %0,{%1,%2};" : "=l"(r) : "f"(lo), "f"(hi)); return r;
}
static __device__ __forceinline__ void upk(ull v, float& lo, float& hi) {
    asm("mov.b64 {%0,%1},%2;" : "=f"(lo), "=f"(hi) : "l"(v));
}
static __device__ __forceinline__ ull fma2(ull a, ull b, ull c) {
    ull d; asm("fma.rn.f32x2 %0,%1,%2,%3;" : "=l"(d) : "l"(a), "l"(b), "l"(c)); return d;
}
static __device__ __forceinline__ ull mul2(ull a, ull b) {
    ull d; asm("mul.rn.f32x2 %0,%1,%2;" : "=l"(d) : "l"(a), "l"(b)); return d;
}

static __device__ __forceinline__ unsigned smem_u32(const void* p) {
    unsigned a;
    asm("{ .reg .u64 t; cvta.to.shared.u64 t, %1; cvt.u32.u64 %0, t; }" : "=r"(a) : "l"(p));
    return a;
}
static __device__ __forceinline__ void cp_async16(unsigned dst, const void* src) {
    asm volatile("cp.async.cg.shared.global [%0], [%1], 16;" :: "r"(dst), "l"(src));
}
static __device__ __forceinline__ void cp_commit() {
    asm volatile("cp.async.commit_group;");
}
template <int N> static __device__ __forceinline__ void cp_wait() {
    asm volatile("cp.async.wait_group %0;" :: "n"(N));
}

#define TPB   128                 // 4 warps
#define RPB   256                 // rows per tile (2 per thread)
#define TILEF (RPB * 32)          // floats per tile buffer (8192) — XOR swizzle, no pad
#define SMEMB (2 * TILEF * 4 + 32 * 8 * 8)   // 65536 + 2048 = 67584 B

__global__ __launch_bounds__(TPB)
void qubit_bloch_kernel(const float* __restrict__ x,
                        const float* __restrict__ theta,
                        const float* __restrict__ w,
                        const float* __restrict__ bias,
                        float* __restrict__ out,
                        int B, int ntiles) {
    extern __shared__ float sm[];             // [2*TILEF] x buffers, then s_c
    float2* s_c = (float2*)&sm[2 * TILEF];    // 32 steps x 8 duplicated f32x2 constants

    const int tid = threadIdx.x;
    const int G   = gridDim.x;

    // ---- per-step RZ(c)∘RY(b) Bloch-rotation constants (once per block) ----
    if (tid < 32) {
        float sb, cb, sc, cc;
        sincosf(theta[2 * tid + 0], &sb, &cb);
        sincosf(theta[2 * tid + 1], &sc, &cc);
        float2* p = &s_c[tid * 8];
        p[0] = make_float2(cc * cb, cc * cb);
        p[1] = make_float2(cc * sb, cc * sb);
        p[2] = make_float2(-sc, -sc);
        p[3] = make_float2(sc * cb, sc * cb);
        p[4] = make_float2(sc * sb, sc * sb);
        p[5] = make_float2(cc, cc);
        p[6] = make_float2(-sb, -sb);
        p[7] = make_float2(cb, cb);
    }

    // precompute this thread's 16 staging slots (row r = k>>3, quad q = k&7)
    // smem float4 slot is XOR-swizzled: slot' = q ^ (r & 7)  -> 16B-aligned cp.async dst
    unsigned dstoff[16];      // byte offsets within a tile buffer
    int      srcoff[16];      // float offsets within a tile's gmem region
    #pragma unroll
    for (int i = 0; i < 16; i++) {
        int k = i * TPB + tid;
        int r = k >> 3, q = k & 7;
        dstoff[i] = (unsigned)((r * 32 + ((q ^ (r & 7)) << 2)) * 4);
        srcoff[i] = r * 32 + q * 4;
    }
    const unsigned sbase = smem_u32(sm);
    const float ww = __ldg(w);
    const float bb = __ldg(bias);

    long tile = blockIdx.x;
    if (tile >= ntiles) return;

    // ---- prologue: stage tile 0 into buffer 0 ----
    {
        const float* src = x + tile * (long)TILEF;
        long rem = (long)B - tile * RPB;                  // rows available
        #pragma unroll
        for (int i = 0; i < 16; i++) {
            const float* s = ((srcoff[i] >> 5) < rem) ? (src + srcoff[i]) : x;
            cp_async16(sbase + dstoff[i], s);
        }
        cp_commit();
    }

    int pbuf = 0;
    for (; tile < ntiles; tile += G) {
        const long next = tile + G;
        const bool have_next = next < ntiles;

        if (have_next) {     // stage next tile into the other buffer (overlaps this compute)
            const float* src = x + next * (long)TILEF;
            long rem = (long)B - next * RPB;
            const unsigned nb = sbase + (unsigned)(pbuf ^ 1) * (TILEF * 4);
            #pragma unroll
            for (int i = 0; i < 16; i++) {
                const float* s = ((srcoff[i] >> 5) < rem) ? (src + srcoff[i]) : x;
                cp_async16(nb + dstoff[i], s);
            }
            cp_commit();
            cp_wait<1>();    // current tile's group done; next stays in flight
        } else {
            cp_wait<0>();
        }
        __syncthreads();     // tile data + (first iter) constants visible

        // ---- compute: 2 rows/thread, packed f32x2 Bloch state, swizzled LDS.128 reads ----
        const float* buf = &sm[pbuf * TILEF];
        const int rA = tid, rB = tid + TPB;
        ull X = pk(0.0f, 0.0f);
        ull Y = X;
        ull Z = pk(1.0f, 1.0f);

        #pragma unroll
        for (int g = 0; g < 8; g++) {          // 8 groups of 4 steps
            float4 a4 = *(const float4*)&buf[rA * 32 + ((g ^ (rA & 7)) << 2)];
            float4 b4 = *(const float4*)&buf[rB * 32 + ((g ^ (rB & 7)) << 2)];
            const float xav[4] = {a4.x, a4.y, a4.z, a4.w};
            const float xbv[4] = {b4.x, b4.y, b4.z, b4.w};
            #pragma unroll
            for (int u = 0; u < 4; u++) {
                const int t = g * 4 + u;
                float sxa, cxa, sxb, cxb;
                __sincosf(xav[u], &sxa, &cxa);
                __sincosf(xbv[u], &sxb, &cxb);
                ull cx  = pk(cxa, cxb);
                ull sx  = pk(sxa, sxb);
                ull nsx = pk(-sxa, -sxb);
                const ulonglong2* C = (const ulonglong2*)&s_c[t * 8];  // 4x LDS.128 bcast
                ulonglong2 c0 = C[0], c1 = C[1], c2 = C[2], c3 = C[3];
                ull Y1 = fma2(cx, Y, mul2(nsx, Z));
                ull Z1 = fma2(cx, Z, mul2(sx, Y));
                ull Xn = fma2(c0.x, X, fma2(c0.y, Z1, mul2(c1.x, Y1)));
                ull Yn = fma2(c1.y, X, fma2(c2.x, Z1, mul2(c2.y, Y1)));
                ull Zn = fma2(c3.y, Z1, mul2(c3.x, X));
                X = Xn; Y = Yn; Z = Zn;
            }
        }

        float za, zb;
        upk(Z, za, zb);
        const long base = tile * RPB;
        if (base + tid < B)       __stcs(&out[base + tid],       za * ww + bb);
        if (base + TPB + tid < B) __stcs(&out[base + TPB + tid], zb * ww + bb);

        __syncthreads();     // all reads of buf[pbuf] done before it is restaged (iter+2)
        pbuf ^= 1;
    }
}

extern "C" void kernel_launch(void* const* d_in, const int* in_sizes, int n_in,
                              void* d_out, int out_size) {
    const float* x     = (const float*)d_in[0];   // [B, 32] f32
    const float* theta = (const float*)d_in[1];   // [32, 2] f32
    const float* w     = (const float*)d_in[2];   // [1, 1]  f32
    const float* b     = (const float*)d_in[3];   // [1]     f32
    float* out = (float*)d_out;

    const int B = in_sizes[0] / 32;
    const int ntiles = (B + RPB - 1) / RPB;

    static int smem_set = 0;
    if (!smem_set) {
        cudaFuncSetAttribute(qubit_bloch_kernel,
                             cudaFuncAttributeMaxDynamicSharedMemorySize, SMEMB);
        smem_set = 1;
    }

    const int persistent = 148 * 3;               // 3 blocks/SM (67.6 KB smem each)
    const int blocks = ntiles < persistent ? ntiles : persistent;
    qubit_bloch_kernel<<<blocks, TPB, SMEMB>>>(x, theta, w, b, out, B, ntiles);
}